// round 4
// baseline (speedup 1.0000x reference)
#include <cuda_runtime.h>
#include <cuda_fp16.h>
#include <cuda_bf16.h>
#include <cstdint>

// Problem constants (fixed shapes)
#define BQ 512
#define NN 131072
#define DD 512
#define KOUT 32

// GEMM tiling (mma.sync path; tcgen05 unavailable: toolchain targets sm_100, not sm_100a)
#define TM 128            // query tile rows
#define TNB 64            // database tile rows
#define KCH 32            // K chunk (elements)
#define NCHUNK (DD / KCH) // 16
#define AST 80            // A smem row stride bytes (32 bf16 = 64B + 16B pad; conflict-free ldmatrix)
#define BST 80
#define OFF_A 0                   // 128*80 = 10240
#define OFF_B (TM * AST)          // 10240, size 64*80 = 5120
#define OFF_SSQ (OFF_B + TNB * BST)   // 15360, 64*4 floats = 1024
#define OFF_SSQB (OFF_SSQ + 1024)     // 16384, 64 floats
#define SMEM_TOT (OFF_SSQB + 256)     // 16640 bytes

// Candidate cap per query
#define CAP 512
#define NBINS 4096

// ---------------- scratch (device globals; no allocation) ----------------
__device__ __half   g_scores[(size_t)BQ * NN];          // 134 MB coarse scores
__device__ uint32_t g_cand[BQ * (CAP + 1)];             // [cnt, idx...] per query

// ---------------- helpers ----------------
__device__ __forceinline__ uint32_t smem_u32(const void* p) {
    uint32_t a;
    asm("{ .reg .u64 t; cvta.to.shared.u64 t, %1; cvt.u32.u64 %0, t; }" : "=r"(a) : "l"(p));
    return a;
}

__device__ __forceinline__ void ldm4(uint32_t* r, uint32_t addr) {
    asm volatile("ldmatrix.sync.aligned.m8n8.x4.shared.b16 {%0,%1,%2,%3}, [%4];"
                 : "=r"(r[0]), "=r"(r[1]), "=r"(r[2]), "=r"(r[3]) : "r"(addr));
}

__device__ __forceinline__ void mma16816(float* c, const uint32_t* a, uint32_t b0, uint32_t b1) {
    asm volatile("mma.sync.aligned.m16n8k16.row.col.f32.bf16.bf16.f32 "
                 "{%0,%1,%2,%3}, {%4,%5,%6,%7}, {%8,%9}, {%0,%1,%2,%3};"
                 : "+f"(c[0]), "+f"(c[1]), "+f"(c[2]), "+f"(c[3])
                 : "r"(a[0]), "r"(a[1]), "r"(a[2]), "r"(a[3]), "r"(b0), "r"(b1));
}

// ---------------- Kernel 1: coarse bf16 distance GEMM (mma.sync) ----------------
// grid (4 qtiles, 2048 ntiles), 256 threads, 2 CTAs/SM
__global__ void __launch_bounds__(256, 2) knn_gemm_kernel(
    const float* __restrict__ q, const float* __restrict__ db)
{
    __shared__ alignas(16) char smem[SMEM_TOT];
    uint32_t sb = smem_u32(smem);
    int tid = threadIdx.x, lane = tid & 31, wid = tid >> 5;
    int qt = blockIdx.x, nt = blockIdx.y;

    // global load assignments
    int a_r = tid >> 1, a_h = tid & 1;          // 2 threads per A row, 16 floats each
    int b_r = tid >> 2, b_q = tid & 3;          // 4 threads per B row, 8 floats each
    const float4* aptr = (const float4*)(q  + (size_t)(qt * TM  + a_r) * DD) + a_h * 4;
    const float4* bptr = (const float4*)(db + (size_t)(nt * TNB + b_r) * DD) + b_q * 2;

    // smem store addresses (bf16, 80B row stride)
    char* sa = smem + OFF_A + a_r * AST + a_h * 32;
    char* sbB = smem + OFF_B + b_r * BST + b_q * 16;

    // ldmatrix base addresses
    int wm = wid & 3, wn = wid >> 2;            // warp tile: 32 m x 64 n
    uint32_t la  = sb + OFF_A + (uint32_t)(wm * 32 + (lane & 15)) * AST + (uint32_t)(lane >> 4) * 16;
    uint32_t lb0 = sb + OFF_B + (uint32_t)(wn * 32 + (lane & 15)) * BST + (uint32_t)(lane >> 4) * 16;
    uint32_t lb1 = lb0 + 16 * BST;

    float c[2][4][4] = {};
    float ssq = 0.f;

    // register prefetch of chunk 0
    float4 pa0 = aptr[0], pa1 = aptr[1], pa2 = aptr[2], pa3 = aptr[3];
    float4 pb0 = bptr[0], pb1 = bptr[1];

    for (int kc = 0; kc < NCHUNK; kc++) {
        // ---- convert + store current chunk to smem ----
        {
            __nv_bfloat162 t0, t1;
            t0 = __floats2bfloat162_rn(pa0.x, pa0.y); t1 = __floats2bfloat162_rn(pa0.z, pa0.w);
            *(uint2*)(sa + 0)  = make_uint2(*(uint32_t*)&t0, *(uint32_t*)&t1);
            t0 = __floats2bfloat162_rn(pa1.x, pa1.y); t1 = __floats2bfloat162_rn(pa1.z, pa1.w);
            *(uint2*)(sa + 8)  = make_uint2(*(uint32_t*)&t0, *(uint32_t*)&t1);
            t0 = __floats2bfloat162_rn(pa2.x, pa2.y); t1 = __floats2bfloat162_rn(pa2.z, pa2.w);
            *(uint2*)(sa + 16) = make_uint2(*(uint32_t*)&t0, *(uint32_t*)&t1);
            t0 = __floats2bfloat162_rn(pa3.x, pa3.y); t1 = __floats2bfloat162_rn(pa3.z, pa3.w);
            *(uint2*)(sa + 24) = make_uint2(*(uint32_t*)&t0, *(uint32_t*)&t1);

            ssq += pb0.x * pb0.x + pb0.y * pb0.y + pb0.z * pb0.z + pb0.w * pb0.w;
            ssq += pb1.x * pb1.x + pb1.y * pb1.y + pb1.z * pb1.z + pb1.w * pb1.w;
            t0 = __floats2bfloat162_rn(pb0.x, pb0.y); t1 = __floats2bfloat162_rn(pb0.z, pb0.w);
            *(uint2*)(sbB + 0) = make_uint2(*(uint32_t*)&t0, *(uint32_t*)&t1);
            t0 = __floats2bfloat162_rn(pb1.x, pb1.y); t1 = __floats2bfloat162_rn(pb1.z, pb1.w);
            *(uint2*)(sbB + 8) = make_uint2(*(uint32_t*)&t0, *(uint32_t*)&t1);
        }
        __syncthreads();

        // ---- prefetch next chunk (overlaps with mma below) ----
        if (kc < NCHUNK - 1) {
            aptr += 8; bptr += 8;
            pa0 = aptr[0]; pa1 = aptr[1]; pa2 = aptr[2]; pa3 = aptr[3];
            pb0 = bptr[0]; pb1 = bptr[1];
        }

        // ---- mma: 2 k-steps of 16 ----
        #pragma unroll
        for (int s = 0; s < 2; s++) {
            uint32_t A0[4], A1[4], B0[4], B1[4];
            ldm4(A0, la + s * 32);
            ldm4(A1, la + 16 * AST + s * 32);
            ldm4(B0, lb0 + s * 32);
            ldm4(B1, lb1 + s * 32);
            mma16816(c[0][0], A0, B0[0], B0[2]);
            mma16816(c[0][1], A0, B0[1], B0[3]);
            mma16816(c[0][2], A0, B1[0], B1[2]);
            mma16816(c[0][3], A0, B1[1], B1[3]);
            mma16816(c[1][0], A1, B0[0], B0[2]);
            mma16816(c[1][1], A1, B0[1], B0[3]);
            mma16816(c[1][2], A1, B1[0], B1[2]);
            mma16816(c[1][3], A1, B1[1], B1[3]);
        }
        __syncthreads();
    }

    // ---- reduce per-row ||d||^2 ----
    ((float*)(smem + OFF_SSQ))[b_r * 4 + b_q] = ssq;
    __syncthreads();
    if (tid < TNB) {
        const float* p = (const float*)(smem + OFF_SSQ) + tid * 4;
        ((float*)(smem + OFF_SSQB))[tid] = p[0] + p[1] + p[2] + p[3];
    }
    __syncthreads();
    const float* ssqB = (const float*)(smem + OFF_SSQB);

    // ---- epilogue: score = ||d||^2 - 2 q.d - 512, fp16 ----
    int m_base = qt * TM + wm * 32 + (lane >> 2);
    int n_base = wn * 32 + 2 * (lane & 3);
    #pragma unroll
    for (int mf = 0; mf < 2; mf++) {
        int m0 = m_base + mf * 16;
        #pragma unroll
        for (int nb = 0; nb < 4; nb++) {
            int n = n_base + nb * 8;
            float sq0 = ssqB[n] - 512.f, sq1 = ssqB[n + 1] - 512.f;
            __half2 h01 = __floats2half2_rn(sq0 - 2.f * c[mf][nb][0], sq1 - 2.f * c[mf][nb][1]);
            __half2 h23 = __floats2half2_rn(sq0 - 2.f * c[mf][nb][2], sq1 - 2.f * c[mf][nb][3]);
            *(__half2*)(g_scores + (size_t)m0 * NN + nt * TNB + n) = h01;
            *(__half2*)(g_scores + (size_t)(m0 + 8) * NN + nt * TNB + n) = h23;
        }
    }
}

// ---------------- Kernel 2: per-query coarse top->=64 selection ----------------
__device__ __forceinline__ uint32_t half_sort_key(uint32_t h) {
    return (h & 0x8000u) ? ((~h) & 0xFFFFu) : (h | 0x8000u);
}

__global__ void __launch_bounds__(256) knn_select_kernel()
{
    __shared__ uint32_t hist[NBINS];
    __shared__ uint32_t buf[CAP];
    __shared__ uint32_t s_cnt, s_cut;
    int tid = threadIdx.x;
    int b = blockIdx.x;

    for (int i = tid; i < NBINS; i += 256) hist[i] = 0;
    if (tid == 0) s_cnt = 0;
    __syncthreads();

    const uint4* row = (const uint4*)(g_scores + (size_t)b * NN);
    // pass 1: histogram of 12-bit sortable keys (warp-aggregated atomics)
    for (int i = tid; i < NN / 8; i += 256) {
        uint4 v = row[i];
        uint32_t w[4] = {v.x, v.y, v.z, v.w};
        #pragma unroll
        for (int s = 0; s < 8; s++) {
            uint32_t h = (w[s >> 1] >> ((s & 1) * 16)) & 0xFFFFu;
            uint32_t bin = half_sort_key(h) >> 4;
            uint32_t mask = __match_any_sync(0xFFFFFFFFu, bin);
            if ((tid & 31) == (__ffs(mask) - 1))
                atomicAdd(&hist[bin], (uint32_t)__popc(mask));
        }
    }
    __syncthreads();
    if (tid == 0) {
        uint32_t c = 0, cut = NBINS - 1;
        for (int i = 0; i < NBINS; i++) { c += hist[i]; if (c >= 64u) { cut = (uint32_t)i; break; } }
        s_cut = cut;
    }
    __syncthreads();
    uint32_t cut = s_cut;

    // pass 2: collect candidate indices below/at cutoff bin
    for (int i = tid; i < NN / 8; i += 256) {
        uint4 v = row[i];
        uint32_t w[4] = {v.x, v.y, v.z, v.w};
        #pragma unroll
        for (int s = 0; s < 8; s++) {
            uint32_t h = (w[s >> 1] >> ((s & 1) * 16)) & 0xFFFFu;
            if ((half_sort_key(h) >> 4) <= cut) {
                uint32_t pos = atomicAdd(&s_cnt, 1u);
                if (pos < CAP) buf[pos] = (uint32_t)(i * 8 + s);
            }
        }
    }
    __syncthreads();
    uint32_t cnt = s_cnt < CAP ? s_cnt : CAP;
    if (tid == 0) g_cand[b * (CAP + 1)] = cnt;
    for (int i = tid; i < (int)cnt; i += 256) g_cand[b * (CAP + 1) + 1 + i] = buf[i];
}

// ---------------- Kernel 3: exact fp32 rescore + top-32 + gather ----------------
__global__ void __launch_bounds__(256) knn_rescore_kernel(
    const float* __restrict__ q, const float* __restrict__ db, float* __restrict__ out)
{
    __shared__ float qs[DD];
    __shared__ unsigned long long arr[CAP];
    __shared__ uint32_t candv[CAP];
    __shared__ uint32_t s_cnt;
    int tid = threadIdx.x, b = blockIdx.x;

    for (int i = tid; i < DD; i += 256) qs[i] = q[(size_t)b * DD + i];
    if (tid == 0) s_cnt = g_cand[b * (CAP + 1)];
    for (int i = tid; i < CAP; i += 256) arr[i] = ~0ull;
    __syncthreads();
    uint32_t cnt = s_cnt;
    for (int i = tid; i < (int)cnt; i += 256) candv[i] = g_cand[b * (CAP + 1) + 1 + i];
    __syncthreads();

    int w = tid >> 5, l = tid & 31;
    const float4* qr = (const float4*)qs;
    for (int c = w; c < (int)cnt; c += 8) {
        uint32_t nidx = candv[c];
        const float4* dr = (const float4*)(db + (size_t)nidx * DD);
        float qd = 0.f, dd = 0.f;
        #pragma unroll
        for (int t = 0; t < 4; t++) {
            float4 dv = dr[t * 32 + l];
            float4 qv = qr[t * 32 + l];
            qd += dv.x * qv.x + dv.y * qv.y + dv.z * qv.z + dv.w * qv.w;
            dd += dv.x * dv.x + dv.y * dv.y + dv.z * dv.z + dv.w * dv.w;
        }
        #pragma unroll
        for (int o = 16; o; o >>= 1) {
            qd += __shfl_xor_sync(0xFFFFFFFFu, qd, o);
            dd += __shfl_xor_sync(0xFFFFFFFFu, dd, o);
        }
        if (l == 0) {
            float s = dd - 2.0f * qd;
            uint32_t fb = __float_as_uint(s);
            fb ^= (fb >> 31) ? 0xFFFFFFFFu : 0x80000000u;
            arr[c] = ((unsigned long long)fb << 32) | (unsigned long long)nidx;
        }
    }
    __syncthreads();

    // bitonic sort CAP=512 u64 keys (ascending exact distance, idx tiebreak)
    for (int k = 2; k <= CAP; k <<= 1)
        for (int j = k >> 1; j > 0; j >>= 1) {
            for (int i = tid; i < CAP; i += 256) {
                int ixj = i ^ j;
                if (ixj > i) {
                    unsigned long long a = arr[i], bb = arr[ixj];
                    bool up = ((i & k) == 0);
                    if ((a > bb) == up) { arr[i] = bb; arr[ixj] = a; }
                }
            }
            __syncthreads();
        }

    // gather top-32 database rows in sorted order
    for (int i = tid; i < KOUT * (DD / 4); i += 256) {
        int j = i >> 7;      // DD/4 = 128 float4 per row
        int e = i & 127;
        uint32_t nidx = (uint32_t)arr[j];
        ((float4*)out)[((size_t)b * KOUT + j) * 128 + e] =
            ((const float4*)db)[(size_t)nidx * 128 + e];
    }
}

// ---------------- launch ----------------
extern "C" void kernel_launch(void* const* d_in, const int* in_sizes, int n_in,
                              void* d_out, int out_size)
{
    const float* q  = (const float*)d_in[0];
    const float* db = (const float*)d_in[1];
    if (n_in >= 2 && in_sizes[0] > in_sizes[1]) {   // defensive: queries is the smaller tensor
        const float* t = q; q = db; db = t;
    }
    float* out = (float*)d_out;

    knn_gemm_kernel<<<dim3(4, NN / TNB), 256>>>(q, db);
    knn_select_kernel<<<BQ, 256>>>();
    knn_rescore_kernel<<<BQ, 256>>>(q, db, out);
}

// round 5
// speedup vs baseline: 2.5631x; 2.5631x over previous
#include <cuda_runtime.h>
#include <cuda_fp16.h>
#include <cuda_bf16.h>
#include <cstdint>

// Problem constants (fixed shapes)
#define BQ 512
#define NN 131072
#define DD 512
#define KOUT 32

// GEMM tiling (mma.sync path; tcgen05 unavailable: toolchain targets sm_100 baseline)
#define TM 128
#define TN 128
#define KCH 64
#define NCHUNK (DD / KCH)   // 8
// smem: double-buffered A(128x64 bf16 = 16KB) + B(16KB) => 64KB dynamic
#define ABUF_BYTES (TM * KCH * 2)
#define BBUF_BYTES (TN * KCH * 2)
#define STAGE_BYTES (ABUF_BYTES + BBUF_BYTES)
#define GEMM_SMEM (2 * STAGE_BYTES)

// Candidate cap per query
#define CAP 512
#define NBINS 4096

// ---------------- scratch (device globals; no allocation) ----------------
__device__ __nv_bfloat16 g_db16[(size_t)NN * DD];   // 134 MB bf16 database
__device__ __nv_bfloat16 g_q16[(size_t)BQ * DD];    // 0.5 MB bf16 queries
__device__ float         g_dbsq[NN];                // db row norms
__device__ __half        g_scores[(size_t)BQ * NN]; // 134 MB coarse scores
__device__ uint32_t      g_cand[BQ * (CAP + 1)];    // [cnt, idx...] per query

// ---------------- helpers ----------------
__device__ __forceinline__ uint32_t smem_u32(const void* p) {
    uint32_t a;
    asm("{ .reg .u64 t; cvta.to.shared.u64 t, %1; cvt.u32.u64 %0, t; }" : "=r"(a) : "l"(p));
    return a;
}
__device__ __forceinline__ void cp_async16(uint32_t dst, const void* src) {
    asm volatile("cp.async.cg.shared.global [%0], [%1], 16;" :: "r"(dst), "l"(src) : "memory");
}
#define CP_COMMIT() asm volatile("cp.async.commit_group;" ::: "memory")
#define CP_WAIT(n)  asm volatile("cp.async.wait_group %0;" :: "n"(n) : "memory")

__device__ __forceinline__ void ldm4(uint32_t* r, uint32_t addr) {
    asm volatile("ldmatrix.sync.aligned.m8n8.x4.shared.b16 {%0,%1,%2,%3}, [%4];"
                 : "=r"(r[0]), "=r"(r[1]), "=r"(r[2]), "=r"(r[3]) : "r"(addr));
}
__device__ __forceinline__ void mma16816(float* c, const uint32_t* a, uint32_t b0, uint32_t b1) {
    asm volatile("mma.sync.aligned.m16n8k16.row.col.f32.bf16.bf16.f32 "
                 "{%0,%1,%2,%3}, {%4,%5,%6,%7}, {%8,%9}, {%0,%1,%2,%3};"
                 : "+f"(c[0]), "+f"(c[1]), "+f"(c[2]), "+f"(c[3])
                 : "r"(a[0]), "r"(a[1]), "r"(a[2]), "r"(a[3]), "r"(b0), "r"(b1));
}

// ---------------- Kernel 0a: db fp32 -> bf16 + row norms ----------------
__global__ void __launch_bounds__(256) prep_db_kernel(const float* __restrict__ db)
{
    int w = (blockIdx.x * 256 + threadIdx.x) >> 5;   // row, 8 warps/block
    int lane = threadIdx.x & 31;
    const float4* src = (const float4*)(db + (size_t)w * DD);
    char* dst = (char*)g_db16 + (size_t)w * (DD * 2);
    float nrm = 0.f;
    #pragma unroll
    for (int i = 0; i < 4; i++) {
        float4 v = src[lane + i * 32];
        nrm += v.x * v.x + v.y * v.y + v.z * v.z + v.w * v.w;
        __nv_bfloat162 a = __floats2bfloat162_rn(v.x, v.y);
        __nv_bfloat162 b = __floats2bfloat162_rn(v.z, v.w);
        *(uint2*)(dst + (lane + i * 32) * 8) = make_uint2(*(uint32_t*)&a, *(uint32_t*)&b);
    }
    #pragma unroll
    for (int o = 16; o; o >>= 1) nrm += __shfl_xor_sync(0xFFFFFFFFu, nrm, o);
    if (lane == 0) g_dbsq[w] = nrm;
}

// ---------------- Kernel 0b: q fp32 -> bf16 ----------------
__global__ void __launch_bounds__(256) prep_q_kernel(const float* __restrict__ q)
{
    int w = (blockIdx.x * 256 + threadIdx.x) >> 5;
    int lane = threadIdx.x & 31;
    const float4* src = (const float4*)(q + (size_t)w * DD);
    char* dst = (char*)g_q16 + (size_t)w * (DD * 2);
    #pragma unroll
    for (int i = 0; i < 4; i++) {
        float4 v = src[lane + i * 32];
        __nv_bfloat162 a = __floats2bfloat162_rn(v.x, v.y);
        __nv_bfloat162 b = __floats2bfloat162_rn(v.z, v.w);
        *(uint2*)(dst + (lane + i * 32) * 8) = make_uint2(*(uint32_t*)&a, *(uint32_t*)&b);
    }
}

// ---------------- Kernel 1: coarse bf16 distance GEMM (cp.async + mma.sync) ----------------
// grid (4 qtiles, 1024 ntiles), 256 threads, 2 CTAs/SM
__global__ void __launch_bounds__(256, 2) knn_gemm_kernel()
{
    extern __shared__ char smem[];
    uint32_t sb = smem_u32(smem);
    int tid = threadIdx.x, lane = tid & 31, wid = tid >> 5;
    int qt = blockIdx.x, nt = blockIdx.y;

    // cp.async assignment: thread t -> row t>>1, 4 consecutive 16B segs
    int cr = tid >> 1;
    int cs0 = (tid & 1) * 4;
    const char* asrc0 = (const char*)g_q16  + ((size_t)(qt * TM + cr) * DD) * 2 + cs0 * 16;
    const char* bsrc0 = (const char*)g_db16 + ((size_t)(nt * TN + cr) * DD) * 2 + cs0 * 16;
    uint32_t adst0 = sb + cr * 128;
    uint32_t bdst0 = sb + ABUF_BYTES + cr * 128;
    uint32_t crx = (uint32_t)(cr & 7);

    // warp tile: 64m x 32n; 8 warps = 2 (m) x 4 (n)
    int wm = wid & 1, wn = wid >> 1;
    int lr = lane & 15;
    uint32_t hi16 = (uint32_t)(lane >> 4) << 4;

    uint32_t aoff[4], arx[4];
    #pragma unroll
    for (int mf = 0; mf < 4; mf++) {
        int row = wm * 64 + mf * 16 + lr;
        aoff[mf] = (uint32_t)row * 128;
        arx[mf] = (uint32_t)(row & 7) << 4;
    }
    uint32_t boff[2], brx[2];
    #pragma unroll
    for (int g = 0; g < 2; g++) {
        int row = wn * 32 + g * 16 + lr;
        boff[g] = (uint32_t)row * 128 + ABUF_BYTES;
        brx[g] = (uint32_t)(row & 7) << 4;
    }

    float c[4][4][4] = {};

    // prologue: stage chunk 0 into buf 0
    {
        #pragma unroll
        for (int i = 0; i < 4; i++) {
            cp_async16(adst0 + ((uint32_t)((cs0 + i) ^ crx) << 4), asrc0 + i * 16);
            cp_async16(bdst0 + ((uint32_t)((cs0 + i) ^ crx) << 4), bsrc0 + i * 16);
        }
        CP_COMMIT();
    }

    #pragma unroll 1
    for (int kc = 0; kc < NCHUNK; kc++) {
        if (kc < NCHUNK - 1) {
            uint32_t bufoff = (uint32_t)((kc + 1) & 1) * STAGE_BYTES;
            const char* as = asrc0 + (size_t)(kc + 1) * 128;
            const char* bs = bsrc0 + (size_t)(kc + 1) * 128;
            #pragma unroll
            for (int i = 0; i < 4; i++) {
                cp_async16(adst0 + bufoff + ((uint32_t)((cs0 + i) ^ crx) << 4), as + i * 16);
                cp_async16(bdst0 + bufoff + ((uint32_t)((cs0 + i) ^ crx) << 4), bs + i * 16);
            }
            CP_COMMIT();
            CP_WAIT(1);
        } else {
            CP_WAIT(0);
        }
        __syncthreads();

        uint32_t base = sb + (uint32_t)(kc & 1) * STAGE_BYTES;
        #pragma unroll
        for (int ks = 0; ks < 4; ks++) {
            uint32_t seg = (uint32_t)(ks << 5) + hi16;
            uint32_t A[4][4], B[2][4];
            #pragma unroll
            for (int mf = 0; mf < 4; mf++) ldm4(A[mf], base + aoff[mf] + (seg ^ arx[mf]));
            #pragma unroll
            for (int g = 0; g < 2; g++) ldm4(B[g], base + boff[g] + (seg ^ brx[g]));
            #pragma unroll
            for (int mf = 0; mf < 4; mf++) {
                mma16816(c[mf][0], A[mf], B[0][0], B[0][2]);
                mma16816(c[mf][1], A[mf], B[0][1], B[0][3]);
                mma16816(c[mf][2], A[mf], B[1][0], B[1][2]);
                mma16816(c[mf][3], A[mf], B[1][1], B[1][3]);
            }
        }
        __syncthreads();
    }

    // epilogue: score = (||d||^2 - 512) - 2 q.d  (q^2 constant per row, dropped)
    int n0l = wn * 32 + 2 * (lane & 3);
    #pragma unroll
    for (int mf = 0; mf < 4; mf++) {
        int m = qt * TM + wm * 64 + mf * 16 + (lane >> 2);
        #pragma unroll
        for (int nf = 0; nf < 4; nf++) {
            int n = nt * TN + n0l + nf * 8;
            float2 dsq = *(const float2*)(g_dbsq + n);
            float s0 = dsq.x - 512.f, s1 = dsq.y - 512.f;
            __half2 h01 = __floats2half2_rn(s0 - 2.f * c[mf][nf][0], s1 - 2.f * c[mf][nf][1]);
            __half2 h23 = __floats2half2_rn(s0 - 2.f * c[mf][nf][2], s1 - 2.f * c[mf][nf][3]);
            *(__half2*)(g_scores + (size_t)m * NN + n) = h01;
            *(__half2*)(g_scores + (size_t)(m + 8) * NN + n) = h23;
        }
    }
}

// ---------------- Kernel 2: per-query coarse top->=64 selection ----------------
__device__ __forceinline__ uint32_t half_sort_key(uint32_t h) {
    return (h & 0x8000u) ? ((~h) & 0xFFFFu) : (h | 0x8000u);
}

__global__ void __launch_bounds__(512) knn_select_kernel()
{
    __shared__ uint32_t hist[NBINS];
    __shared__ uint32_t psum[256];
    __shared__ uint32_t buf[CAP];
    __shared__ uint32_t s_cnt, s_cut;
    int tid = threadIdx.x;
    int b = blockIdx.x;

    for (int i = tid; i < NBINS; i += 512) hist[i] = 0;
    if (tid == 0) s_cnt = 0;
    __syncthreads();

    const uint4* row = (const uint4*)(g_scores + (size_t)b * NN);
    // pass 1: direct histogram of 12-bit sortable keys
    for (int i = tid; i < NN / 8; i += 512) {
        uint4 v = row[i];
        uint32_t w[4] = {v.x, v.y, v.z, v.w};
        #pragma unroll
        for (int s = 0; s < 8; s++) {
            uint32_t h = (w[s >> 1] >> ((s & 1) * 16)) & 0xFFFFu;
            atomicAdd(&hist[half_sort_key(h) >> 4], 1u);
        }
    }
    __syncthreads();
    // parallel cutoff: 256 partial sums of 16 bins, then short serial scan
    if (tid < 256) {
        uint32_t s = 0;
        #pragma unroll
        for (int j = 0; j < 16; j++) s += hist[tid * 16 + j];
        psum[tid] = s;
    }
    __syncthreads();
    if (tid == 0) {
        uint32_t c = 0, cut = NBINS - 1;
        int seg = 0;
        for (; seg < 256; seg++) { if (c + psum[seg] >= 64u) break; c += psum[seg]; }
        if (seg < 256) {
            int j = 0;
            for (; j < 16; j++) { c += hist[seg * 16 + j]; if (c >= 64u) break; }
            cut = (uint32_t)(seg * 16 + (j < 16 ? j : 15));
        }
        s_cut = cut;
    }
    __syncthreads();
    uint32_t cut = s_cut;

    // pass 2: collect candidate indices below/at cutoff bin
    for (int i = tid; i < NN / 8; i += 512) {
        uint4 v = row[i];
        uint32_t w[4] = {v.x, v.y, v.z, v.w};
        #pragma unroll
        for (int s = 0; s < 8; s++) {
            uint32_t h = (w[s >> 1] >> ((s & 1) * 16)) & 0xFFFFu;
            if ((half_sort_key(h) >> 4) <= cut) {
                uint32_t pos = atomicAdd(&s_cnt, 1u);
                if (pos < CAP) buf[pos] = (uint32_t)(i * 8 + s);
            }
        }
    }
    __syncthreads();
    uint32_t cnt = s_cnt < CAP ? s_cnt : CAP;
    if (tid == 0) g_cand[b * (CAP + 1)] = cnt;
    for (int i = tid; i < (int)cnt; i += 512) g_cand[b * (CAP + 1) + 1 + i] = buf[i];
}

// ---------------- Kernel 3: exact fp32 rescore + top-32 + gather ----------------
__global__ void __launch_bounds__(256) knn_rescore_kernel(
    const float* __restrict__ q, const float* __restrict__ db, float* __restrict__ out)
{
    __shared__ float qs[DD];
    __shared__ unsigned long long arr[CAP];
    __shared__ uint32_t candv[CAP];
    __shared__ uint32_t s_cnt;
    int tid = threadIdx.x, b = blockIdx.x;

    for (int i = tid; i < DD; i += 256) qs[i] = q[(size_t)b * DD + i];
    if (tid == 0) s_cnt = g_cand[b * (CAP + 1)];
    for (int i = tid; i < CAP; i += 256) arr[i] = ~0ull;
    __syncthreads();
    uint32_t cnt = s_cnt;
    for (int i = tid; i < (int)cnt; i += 256) candv[i] = g_cand[b * (CAP + 1) + 1 + i];
    __syncthreads();

    int w = tid >> 5, l = tid & 31;
    const float4* qr = (const float4*)qs;
    for (int c = w; c < (int)cnt; c += 8) {
        uint32_t nidx = candv[c];
        const float4* dr = (const float4*)(db + (size_t)nidx * DD);
        float qd = 0.f, dd = 0.f;
        #pragma unroll
        for (int t = 0; t < 4; t++) {
            float4 dv = dr[t * 32 + l];
            float4 qv = qr[t * 32 + l];
            qd += dv.x * qv.x + dv.y * qv.y + dv.z * qv.z + dv.w * qv.w;
            dd += dv.x * dv.x + dv.y * dv.y + dv.z * dv.z + dv.w * dv.w;
        }
        #pragma unroll
        for (int o = 16; o; o >>= 1) {
            qd += __shfl_xor_sync(0xFFFFFFFFu, qd, o);
            dd += __shfl_xor_sync(0xFFFFFFFFu, dd, o);
        }
        if (l == 0) {
            float s = dd - 2.0f * qd;
            uint32_t fb = __float_as_uint(s);
            fb ^= (fb >> 31) ? 0xFFFFFFFFu : 0x80000000u;
            arr[c] = ((unsigned long long)fb << 32) | (unsigned long long)nidx;
        }
    }
    __syncthreads();

    // bitonic sort CAP=512 u64 keys (ascending exact distance, idx tiebreak)
    for (int k = 2; k <= CAP; k <<= 1)
        for (int j = k >> 1; j > 0; j >>= 1) {
            for (int i = tid; i < CAP; i += 256) {
                int ixj = i ^ j;
                if (ixj > i) {
                    unsigned long long a = arr[i], bb = arr[ixj];
                    bool up = ((i & k) == 0);
                    if ((a > bb) == up) { arr[i] = bb; arr[ixj] = a; }
                }
            }
            __syncthreads();
        }

    // gather top-32 database rows in sorted order
    for (int i = tid; i < KOUT * (DD / 4); i += 256) {
        int j = i >> 7;      // DD/4 = 128 float4 per row
        int e = i & 127;
        uint32_t nidx = (uint32_t)arr[j];
        ((float4*)out)[((size_t)b * KOUT + j) * 128 + e] =
            ((const float4*)db)[(size_t)nidx * 128 + e];
    }
}

// ---------------- launch ----------------
extern "C" void kernel_launch(void* const* d_in, const int* in_sizes, int n_in,
                              void* d_out, int out_size)
{
    const float* q  = (const float*)d_in[0];
    const float* db = (const float*)d_in[1];
    if (n_in >= 2 && in_sizes[0] > in_sizes[1]) {   // defensive: queries is the smaller tensor
        const float* t = q; q = db; db = t;
    }
    float* out = (float*)d_out;

    cudaFuncSetAttribute(knn_gemm_kernel, cudaFuncAttributeMaxDynamicSharedMemorySize, GEMM_SMEM);

    prep_db_kernel<<<NN / 8, 256>>>(db);
    prep_q_kernel<<<BQ / 8, 256>>>(q);
    knn_gemm_kernel<<<dim3(4, NN / TN), 256, GEMM_SMEM>>>();
    knn_select_kernel<<<BQ, 512>>>();
    knn_rescore_kernel<<<BQ, 256>>>(q, db, out);
}